// round 1
// baseline (speedup 1.0000x reference)
#include <cuda_runtime.h>
#include <stdint.h>

// ============================================================================
// Radix-select threshold kernel.
// thresh = (max_features)-th entry (0-based) of the descending sort of all
// inputs concatenated. out[i] = x[i] < thresh ? 0 : x[i].
//
// Float -> order-preserving uint key: key = u ^ (sign ? 0xFFFFFFFF : 0x80000000)
// Descending float order == descending key order.
// ============================================================================

#define SCRATCH_CAP (16u * 1024u * 1024u)   // 64 MB static scratch (keys)

__device__ unsigned int g_hist[256];
__device__ unsigned int g_scratch[SCRATCH_CAP];
__device__ unsigned int g_nscratch;
__device__ unsigned int g_key;      // accumulated key prefix (value, not shifted)
__device__ unsigned int g_rank;     // residual rank within current bracket
__device__ int          g_done;     // 1 => thresh already decided (mf >= n)
__device__ float        g_thresh;

__device__ __forceinline__ unsigned int fmap_u(unsigned int u) {
    // sign set:   ~u ;  sign clear: u | 0x80000000
    return u ^ ((unsigned int)((int)u >> 31) | 0x80000000u);
}
__device__ __forceinline__ float finv_map(unsigned int k) {
    unsigned int u = (k & 0x80000000u) ? (k ^ 0x80000000u) : ~k;
    return __uint_as_float(u);
}
__device__ __forceinline__ unsigned int warp_sum(unsigned int v) {
    v += __shfl_xor_sync(0xFFFFFFFFu, v, 16);
    v += __shfl_xor_sync(0xFFFFFFFFu, v, 8);
    v += __shfl_xor_sync(0xFFFFFFFFu, v, 4);
    v += __shfl_xor_sync(0xFFFFFFFFu, v, 2);
    v += __shfl_xor_sync(0xFFFFFFFFu, v, 1);
    return v;
}

// Packed 16-bin counter: 4 x u32, each holding 4 x 8-bit counts.
// Per-thread element count must stay < 255 per bin (it is: <= ~84 total).
__device__ __forceinline__ void acc16(unsigned int bin,
                                      unsigned int& c0, unsigned int& c1,
                                      unsigned int& c2, unsigned int& c3) {
    unsigned int inc = 1u << ((bin & 3u) << 3);
    unsigned int j = bin >> 2;
    if (j == 0)      c0 += inc;
    else if (j == 1) c1 += inc;
    else if (j == 2) c2 += inc;
    else             c3 += inc;
}

__device__ __forceinline__ void flush16(unsigned int c0, unsigned int c1,
                                        unsigned int c2, unsigned int c3) {
    __shared__ unsigned int sh[16];
    if (threadIdx.x < 16) sh[threadIdx.x] = 0;
    __syncthreads();
    unsigned int lane = threadIdx.x & 31;
    unsigned int cc[4] = {c0, c1, c2, c3};
#pragma unroll
    for (int k = 0; k < 16; k++) {
        unsigned int v = (cc[k >> 2] >> ((k & 3) * 8)) & 0xFFu;
        v = warp_sum(v);
        if (lane == 0 && v) atomicAdd(&sh[k], v);
    }
    __syncthreads();
    if (threadIdx.x < 16 && sh[threadIdx.x]) atomicAdd(&g_hist[threadIdx.x], sh[threadIdx.x]);
}

// ---------------------------------------------------------------------------
__global__ void k_init() {
    int i = blockIdx.x * blockDim.x + threadIdx.x;
    if (i < 256) g_hist[i] = 0;
    if (i == 0) { g_nscratch = 0; g_done = 0; g_key = 0; g_rank = 0; }
}

// ---------------------------------------------------------------------------
// P1: 16-bin count on top 4 bits of key, over all three arrays.
__global__ void k_count_top(const uint4* __restrict__ a0, int n0,
                            const uint4* __restrict__ a1, int n1,
                            const uint4* __restrict__ a2, int n2) {
    unsigned int c0 = 0, c1 = 0, c2 = 0, c3 = 0;
    int tid = blockIdx.x * blockDim.x + threadIdx.x;
    int stride = gridDim.x * blockDim.x;

#define P1_BODY(ARR, N)                                                     \
    for (int i = tid; i < (N); i += stride) {                               \
        uint4 v = (ARR)[i];                                                 \
        acc16(fmap_u(v.x) >> 28, c0, c1, c2, c3);                           \
        acc16(fmap_u(v.y) >> 28, c0, c1, c2, c3);                           \
        acc16(fmap_u(v.z) >> 28, c0, c1, c2, c3);                           \
        acc16(fmap_u(v.w) >> 28, c0, c1, c2, c3);                           \
    }
    P1_BODY(a0, n0)
    P1_BODY(a1, n1)
    P1_BODY(a2, n2)
#undef P1_BODY
    flush16(c0, c1, c2, c3);
}

// ---------------------------------------------------------------------------
// S1: pick bracket among 16 top bins; handle mf >= n. Then zero hist.
__global__ void k_select1(const int* mf_ptr, int host_mf, long long ntotal) {
    if (threadIdx.x == 0) {
        long long mf = (mf_ptr != nullptr) ? (long long)(*mf_ptr) : (long long)host_mf;
        if (mf >= ntotal) {
            g_done = 1;
            g_thresh = 0.0f;
        } else {
            unsigned int r = (unsigned int)mf;
            int sel = 0;
            for (int b = 15; b >= 0; b--) {
                unsigned int c = g_hist[b];
                if (r < c) { sel = b; break; }
                r -= c;
            }
            g_key = (unsigned int)sel;
            g_rank = r;
        }
    }
    __syncthreads();
    if (threadIdx.x < 256) g_hist[threadIdx.x] = 0;
}

// ---------------------------------------------------------------------------
// P2: among elements whose top-4-bit key prefix matches g_key, count 16 bins
// on bits [27:24] AND compact their keys into g_scratch.
__global__ void k_count_compact(const uint4* __restrict__ a0, int n0,
                                const uint4* __restrict__ a1, int n1,
                                const uint4* __restrict__ a2, int n2) {
    if (g_done) return;
    const unsigned int pref = g_key;   // 4-bit prefix
    unsigned int c0 = 0, c1 = 0, c2 = 0, c3 = 0;
    int tid = blockIdx.x * blockDim.x + threadIdx.x;
    int stride = gridDim.x * blockDim.x;
    unsigned int lane = threadIdx.x & 31;

#define P2_BODY(ARR, N)                                                        \
    for (int i = tid; i < (N); i += stride) {                                  \
        uint4 v = (ARR)[i];                                                    \
        unsigned int k0 = fmap_u(v.x), k1 = fmap_u(v.y);                       \
        unsigned int k2 = fmap_u(v.z), k3 = fmap_u(v.w);                       \
        bool in0 = (k0 >> 28) == pref, in1 = (k1 >> 28) == pref;               \
        bool in2 = (k2 >> 28) == pref, in3 = (k3 >> 28) == pref;               \
        if (in0) acc16((k0 >> 24) & 15u, c0, c1, c2, c3);                      \
        if (in1) acc16((k1 >> 24) & 15u, c0, c1, c2, c3);                      \
        if (in2) acc16((k2 >> 24) & 15u, c0, c1, c2, c3);                      \
        if (in3) acc16((k3 >> 24) & 15u, c0, c1, c2, c3);                      \
        unsigned int cnt = (unsigned)in0 + (unsigned)in1 +                     \
                           (unsigned)in2 + (unsigned)in3;                      \
        unsigned int incl = cnt;                                               \
        for (int o = 1; o < 32; o <<= 1) {                                     \
            unsigned int t = __shfl_up_sync(0xFFFFFFFFu, incl, o);             \
            if (lane >= (unsigned)o) incl += t;                                \
        }                                                                      \
        unsigned int total = __shfl_sync(0xFFFFFFFFu, incl, 31);               \
        if (total) {                                                           \
            unsigned int base = 0;                                             \
            if (lane == 31) base = atomicAdd(&g_nscratch, total);              \
            base = __shfl_sync(0xFFFFFFFFu, base, 31);                         \
            unsigned int off = base + incl - cnt;                              \
            if (in0 && off < SCRATCH_CAP) g_scratch[off++] = k0;               \
            if (in1 && off < SCRATCH_CAP) g_scratch[off++] = k1;               \
            if (in2 && off < SCRATCH_CAP) g_scratch[off++] = k2;               \
            if (in3 && off < SCRATCH_CAP) g_scratch[off++] = k3;               \
        }                                                                      \
    }
    P2_BODY(a0, n0)
    P2_BODY(a1, n1)
    P2_BODY(a2, n2)
#undef P2_BODY
    flush16(c0, c1, c2, c3);
}

// ---------------------------------------------------------------------------
// Generic select over nbins (16 or 256). final==1 -> derive the float thresh.
__global__ void k_select(int nbins, int final_stage) {
    if (threadIdx.x == 0 && !g_done) {
        unsigned int r = g_rank;
        int sel = 0;
        for (int b = nbins - 1; b >= 0; b--) {
            unsigned int c = g_hist[b];
            if (r < c) { sel = b; break; }
            r -= c;
        }
        g_key = g_key * (unsigned int)nbins + (unsigned int)sel;
        g_rank = r;
        if (final_stage) g_thresh = finv_map(g_key);
    }
    __syncthreads();
    if (threadIdx.x < 256) g_hist[threadIdx.x] = 0;
}

// ---------------------------------------------------------------------------
// P3/P4/P5: 256-bin smem histogram over scratch keys matching current prefix.
// shift = 16, 8, 0; prefix compare at (shift + 8).
__global__ void k_scratch_hist(int shift) {
    if (g_done) return;
    __shared__ unsigned int sh[256];
    for (int i = threadIdx.x; i < 256; i += blockDim.x) sh[i] = 0;
    __syncthreads();
    unsigned int n = g_nscratch;
    if (n > SCRATCH_CAP) n = SCRATCH_CAP;
    const unsigned int pref = g_key;
    for (unsigned int i = blockIdx.x * blockDim.x + threadIdx.x; i < n;
         i += gridDim.x * blockDim.x) {
        unsigned int key = g_scratch[i];
        if ((key >> (shift + 8)) == pref)
            atomicAdd(&sh[(key >> shift) & 255u], 1u);
    }
    __syncthreads();
    for (int i = threadIdx.x; i < 256; i += blockDim.x)
        if (sh[i]) atomicAdd(&g_hist[i], sh[i]);
}

// ---------------------------------------------------------------------------
// P6: threshold write, concatenated output.
__global__ void k_threshold(const float4* __restrict__ a0, int n0,
                            const float4* __restrict__ a1, int n1,
                            const float4* __restrict__ a2, int n2,
                            float4* __restrict__ out) {
    const float th = g_thresh;
    int tid = blockIdx.x * blockDim.x + threadIdx.x;
    int stride = gridDim.x * blockDim.x;
    for (int i = tid; i < n0; i += stride) {
        float4 v = a0[i];
        v.x = (v.x < th) ? 0.0f : v.x;  v.y = (v.y < th) ? 0.0f : v.y;
        v.z = (v.z < th) ? 0.0f : v.z;  v.w = (v.w < th) ? 0.0f : v.w;
        out[i] = v;
    }
    float4* o1 = out + n0;
    for (int i = tid; i < n1; i += stride) {
        float4 v = a1[i];
        v.x = (v.x < th) ? 0.0f : v.x;  v.y = (v.y < th) ? 0.0f : v.y;
        v.z = (v.z < th) ? 0.0f : v.z;  v.w = (v.w < th) ? 0.0f : v.w;
        o1[i] = v;
    }
    float4* o2 = out + n0 + n1;
    for (int i = tid; i < n2; i += stride) {
        float4 v = a2[i];
        v.x = (v.x < th) ? 0.0f : v.x;  v.y = (v.y < th) ? 0.0f : v.y;
        v.z = (v.z < th) ? 0.0f : v.z;  v.w = (v.w < th) ? 0.0f : v.w;
        o2[i] = v;
    }
}

// ============================================================================
extern "C" void kernel_launch(void* const* d_in, const int* in_sizes, int n_in,
                              void* d_out, int out_size) {
    const float* e  = (const float*)d_in[0];
    const float* m  = (const float*)d_in[1];
    const float* dp = (const float*)d_in[2];
    const int* mf_ptr = (n_in >= 4) ? (const int*)d_in[3] : nullptr;
    int ne = in_sizes[0], nm = in_sizes[1], nd = in_sizes[2];
    long long ntot = (long long)ne + (long long)nm + (long long)nd;
    int ne4 = ne / 4, nm4 = nm / 4, nd4 = nd / 4;

    const uint4* u0 = (const uint4*)e;
    const uint4* u1 = (const uint4*)m;
    const uint4* u2 = (const uint4*)dp;

    k_init<<<1, 256>>>();
    k_count_top<<<1024, 256>>>(u0, ne4, u1, nm4, u2, nd4);
    k_select1<<<1, 256>>>(mf_ptr, 500000, ntot);
    k_count_compact<<<1024, 256>>>(u0, ne4, u1, nm4, u2, nd4);
    k_select<<<1, 256>>>(16, 0);
    k_scratch_hist<<<256, 256>>>(16);
    k_select<<<1, 256>>>(256, 0);
    k_scratch_hist<<<256, 256>>>(8);
    k_select<<<1, 256>>>(256, 0);
    k_scratch_hist<<<256, 256>>>(0);
    k_select<<<1, 256>>>(256, 1);
    k_threshold<<<2048, 256>>>((const float4*)e, ne4, (const float4*)m, nm4,
                               (const float4*)dp, nd4, (float4*)d_out);
}

// round 2
// speedup vs baseline: 1.8613x; 1.8613x over previous
#include <cuda_runtime.h>
#include <stdint.h>

// ============================================================================
// Speculative radix-select threshold kernel.
// thresh = (max_features)-th entry (0-based) of the descending sort of all
// inputs concatenated. out[i] = x[i] < thresh ? 0 : x[i].
//
// Float -> order-preserving uint key: key = u ^ (sign ? 0xFFFFFFFF : 0x80000000)
// Descending float order == descending key order.
//
// Spec path: single full read compacts all keys >= key(1.0f) into per-warp
// scratch slices. Valid iff n_scratch >= mf+1 (checked exactly on device).
// Fallback path (device-gated): 256-bin full hist -> prefix compact.
// Then 8-bit radix passes over scratch resolve the exact 32-bit key.
// ============================================================================

#define NB       1024
#define NT       256
#define NWARP    (NB * NT / 32)            // 8192 warps
#define SLICE    2048u                     // entries per warp slice
#define SCRATCH_CAP (NWARP * SLICE)        // 16M keys = 64 MB
#define SPEC_KEY 0xBF800000u               // key of +1.0f

__device__ unsigned int g_hist[256];
__device__ unsigned int g_scratch[SCRATCH_CAP];
__device__ unsigned int g_warpcnt[NWARP];
__device__ unsigned int g_nscratch;
__device__ unsigned int g_key;     // accumulated known high bits (right-aligned)
__device__ unsigned int g_rank;    // residual rank within current bracket
__device__ int          g_mode;    // 0=spec ok, 1=fallback, 2=trivial(thresh=0)
__device__ int          g_overflow;
__device__ float        g_thresh;

__device__ __forceinline__ unsigned int fmap_u(unsigned int u) {
    return u ^ ((unsigned int)((int)u >> 31) | 0x80000000u);
}
__device__ __forceinline__ float finv_map(unsigned int k) {
    unsigned int u = (k & 0x80000000u) ? (k ^ 0x80000000u) : ~k;
    return __uint_as_float(u);
}

// ---------------------------------------------------------------------------
__global__ void k_init() {
    int i = blockIdx.x * blockDim.x + threadIdx.x;
    if (i < 256) g_hist[i] = 0;
    if (i == 0) {
        g_nscratch = 0; g_mode = 0; g_key = 0; g_rank = 0;
        g_overflow = 0; g_thresh = 0.0f;
    }
}

// ---------------------------------------------------------------------------
// Pass 1 (speculative): compact all keys >= SPEC_KEY into per-warp slices.
// No scans, no hot-loop atomics: 4 independent ballots + popc offsets.
__global__ void __launch_bounds__(NT) k_spec_compact(
        const uint4* __restrict__ a0, int n0,
        const uint4* __restrict__ a1, int n1,
        const uint4* __restrict__ a2, int n2) {
    int tid = blockIdx.x * blockDim.x + threadIdx.x;
    int stride = gridDim.x * blockDim.x;
    unsigned int lane = threadIdx.x & 31u;
    unsigned int gw = (unsigned int)tid >> 5;
    unsigned int base = gw * SLICE;
    unsigned int lt = (lane == 31u) ? 0x7FFFFFFFu : ((1u << lane) - 1u);
    unsigned int me = 1u << lane;
    unsigned int wo = 0;   // warp-uniform running offset

#define SPEC_BODY(ARR, N)                                                     \
    for (int i = tid; i < (N); i += stride) {                                 \
        uint4 v = (ARR)[i];                                                   \
        unsigned int k0 = fmap_u(v.x), k1 = fmap_u(v.y);                      \
        unsigned int k2 = fmap_u(v.z), k3 = fmap_u(v.w);                      \
        unsigned int b0 = __ballot_sync(0xFFFFFFFFu, k0 >= SPEC_KEY);         \
        unsigned int b1 = __ballot_sync(0xFFFFFFFFu, k1 >= SPEC_KEY);         \
        unsigned int b2 = __ballot_sync(0xFFFFFFFFu, k2 >= SPEC_KEY);         \
        unsigned int b3 = __ballot_sync(0xFFFFFFFFu, k3 >= SPEC_KEY);         \
        unsigned int t0 = __popc(b0), t1 = __popc(b1);                        \
        unsigned int t2 = __popc(b2), t3 = __popc(b3);                        \
        unsigned int tot = t0 + t1 + t2 + t3;                                 \
        if (tot) {                                                            \
            if (wo + tot <= SLICE) {                                          \
                unsigned int o = base + wo;                                   \
                if (b0 & me) g_scratch[o + __popc(b0 & lt)] = k0;             \
                o += t0;                                                      \
                if (b1 & me) g_scratch[o + __popc(b1 & lt)] = k1;             \
                o += t1;                                                      \
                if (b2 & me) g_scratch[o + __popc(b2 & lt)] = k2;             \
                o += t2;                                                      \
                if (b3 & me) g_scratch[o + __popc(b3 & lt)] = k3;             \
                wo += tot;                                                    \
            } else {                                                          \
                g_overflow = 1;                                               \
            }                                                                 \
        }                                                                     \
    }
    SPEC_BODY(a0, n0)
    SPEC_BODY(a1, n1)
    SPEC_BODY(a2, n2)
#undef SPEC_BODY

    if (lane == 0) {
        g_warpcnt[gw] = wo;
        atomicAdd(&g_nscratch, wo);
    }
}

// ---------------------------------------------------------------------------
// Decide mode. mode 0: rank=mf over scratch. mode 1: fallback. mode 2: thresh=0.
__global__ void k_select_spec(const int* mf_ptr, int host_mf, long long ntot) {
    if (threadIdx.x == 0) {
        long long mf = (mf_ptr != nullptr) ? (long long)(*mf_ptr)
                                           : (long long)host_mf;
        if (mf >= ntot) {
            g_mode = 2; g_thresh = 0.0f;
        } else if (g_overflow || (long long)g_nscratch < mf + 1) {
            g_mode = 1;
        } else {
            g_mode = 0; g_rank = (unsigned int)mf; g_key = 0;
        }
    }
    __syncthreads();
    if (threadIdx.x < 256) g_hist[threadIdx.x] = 0;
}

// ---------------------------------------------------------------------------
// FALLBACK: full 256-bin hist on top 8 key bits (perf irrelevant; gated off
// on the spec-valid path).
__global__ void __launch_bounds__(NT) k_fb_hist256(
        const uint4* __restrict__ a0, int n0,
        const uint4* __restrict__ a1, int n1,
        const uint4* __restrict__ a2, int n2) {
    if (g_mode != 1) return;
    __shared__ unsigned int sh[256];
    for (int i = threadIdx.x; i < 256; i += blockDim.x) sh[i] = 0;
    __syncthreads();
    int tid = blockIdx.x * blockDim.x + threadIdx.x;
    int stride = gridDim.x * blockDim.x;
#define FB_BODY(ARR, N)                                                       \
    for (int i = tid; i < (N); i += stride) {                                 \
        uint4 v = (ARR)[i];                                                   \
        atomicAdd(&sh[fmap_u(v.x) >> 24], 1u);                                \
        atomicAdd(&sh[fmap_u(v.y) >> 24], 1u);                                \
        atomicAdd(&sh[fmap_u(v.z) >> 24], 1u);                                \
        atomicAdd(&sh[fmap_u(v.w) >> 24], 1u);                                \
    }
    FB_BODY(a0, n0)
    FB_BODY(a1, n1)
    FB_BODY(a2, n2)
#undef FB_BODY
    __syncthreads();
    for (int i = threadIdx.x; i < 256; i += blockDim.x)
        if (sh[i]) atomicAdd(&g_hist[i], sh[i]);
}

__global__ void k_fb_select(const int* mf_ptr, int host_mf) {
    if (g_mode != 1) return;
    if (threadIdx.x == 0) {
        unsigned int r = (mf_ptr != nullptr) ? (unsigned int)(*mf_ptr)
                                             : (unsigned int)host_mf;
        int sel = 0;
        for (int b = 255; b >= 0; b--) {
            unsigned int c = g_hist[b];
            if (r < c) { sel = b; break; }
            r -= c;
        }
        g_key = (unsigned int)sel;   // 8 known bits
        g_rank = r;
    }
    __syncthreads();
    if (threadIdx.x < 256) g_hist[threadIdx.x] = 0;
}

// FALLBACK compact: keys whose top 8 bits == g_key, into per-warp slices.
__global__ void __launch_bounds__(NT) k_fb_compact(
        const uint4* __restrict__ a0, int n0,
        const uint4* __restrict__ a1, int n1,
        const uint4* __restrict__ a2, int n2) {
    if (g_mode != 1) return;
    const unsigned int pref = g_key;
    int tid = blockIdx.x * blockDim.x + threadIdx.x;
    int stride = gridDim.x * blockDim.x;
    unsigned int lane = threadIdx.x & 31u;
    unsigned int gw = (unsigned int)tid >> 5;
    unsigned int base = gw * SLICE;
    unsigned int lt = (lane == 31u) ? 0x7FFFFFFFu : ((1u << lane) - 1u);
    unsigned int me = 1u << lane;
    unsigned int wo = 0;

#define FBC_BODY(ARR, N)                                                      \
    for (int i = tid; i < (N); i += stride) {                                 \
        uint4 v = (ARR)[i];                                                   \
        unsigned int k0 = fmap_u(v.x), k1 = fmap_u(v.y);                      \
        unsigned int k2 = fmap_u(v.z), k3 = fmap_u(v.w);                      \
        unsigned int b0 = __ballot_sync(0xFFFFFFFFu, (k0 >> 24) == pref);     \
        unsigned int b1 = __ballot_sync(0xFFFFFFFFu, (k1 >> 24) == pref);     \
        unsigned int b2 = __ballot_sync(0xFFFFFFFFu, (k2 >> 24) == pref);     \
        unsigned int b3 = __ballot_sync(0xFFFFFFFFu, (k3 >> 24) == pref);     \
        unsigned int t0 = __popc(b0), t1 = __popc(b1);                        \
        unsigned int t2 = __popc(b2), t3 = __popc(b3);                        \
        unsigned int tot = t0 + t1 + t2 + t3;                                 \
        if (tot && wo + tot <= SLICE) {                                       \
            unsigned int o = base + wo;                                       \
            if (b0 & me) g_scratch[o + __popc(b0 & lt)] = k0;                 \
            o += t0;                                                          \
            if (b1 & me) g_scratch[o + __popc(b1 & lt)] = k1;                 \
            o += t1;                                                          \
            if (b2 & me) g_scratch[o + __popc(b2 & lt)] = k2;                 \
            o += t2;                                                          \
            if (b3 & me) g_scratch[o + __popc(b3 & lt)] = k3;                 \
            wo += tot;                                                        \
        }                                                                     \
    }
    FBC_BODY(a0, n0)
    FBC_BODY(a1, n1)
    FBC_BODY(a2, n2)
#undef FBC_BODY

    if (lane == 0) g_warpcnt[gw] = wo;
}

// ---------------------------------------------------------------------------
// 256-bin hist over scratch slices at given shift, with prefix compare.
// shift==24 runs only in mode 0 (no prefix known yet).
__global__ void __launch_bounds__(NT) k_hist_slices(int shift, int mode0_only) {
    int mode = g_mode;
    if (mode == 2) return;
    if (mode0_only && mode != 0) return;
    __shared__ unsigned int sh[256];
    for (int i = threadIdx.x; i < 256; i += blockDim.x) sh[i] = 0;
    __syncthreads();

    unsigned int lane = threadIdx.x & 31u;
    unsigned int warp = threadIdx.x >> 5;
    unsigned int slice = blockIdx.x * (blockDim.x >> 5) + warp;
    if (slice < NWARP) {
        unsigned int cnt = g_warpcnt[slice];
        if (cnt > SLICE) cnt = SLICE;
        const unsigned int pref = g_key;
        unsigned int sbase = slice * SLICE;
        if (shift == 24) {
            for (unsigned int i = lane; i < cnt; i += 32) {
                unsigned int key = g_scratch[sbase + i];
                atomicAdd(&sh[key >> 24], 1u);
            }
        } else {
            for (unsigned int i = lane; i < cnt; i += 32) {
                unsigned int key = g_scratch[sbase + i];
                if ((key >> (shift + 8)) == pref)
                    atomicAdd(&sh[(key >> shift) & 255u], 1u);
            }
        }
    }
    __syncthreads();
    for (int i = threadIdx.x; i < 256; i += blockDim.x)
        if (sh[i]) atomicAdd(&g_hist[i], sh[i]);
}

// ---------------------------------------------------------------------------
// Select among 256 bins, append 8 bits to g_key, zero hist.
__global__ void k_select8(int final_stage, int mode0_only) {
    int mode = g_mode;
    if (mode != 2 && !(mode0_only && mode != 0)) {
        if (threadIdx.x == 0) {
            unsigned int r = g_rank;
            int sel = 0;
            for (int b = 255; b >= 0; b--) {
                unsigned int c = g_hist[b];
                if (r < c) { sel = b; break; }
                r -= c;
            }
            g_key = (g_key << 8) | (unsigned int)sel;
            g_rank = r;
            if (final_stage) g_thresh = finv_map(g_key);
        }
    }
    __syncthreads();
    if (threadIdx.x < 256) g_hist[threadIdx.x] = 0;
}

// ---------------------------------------------------------------------------
// Final pass: threshold write, concatenated output.
__global__ void __launch_bounds__(NT) k_threshold(
        const float4* __restrict__ a0, int n0,
        const float4* __restrict__ a1, int n1,
        const float4* __restrict__ a2, int n2,
        float4* __restrict__ out) {
    const float th = g_thresh;
    int tid = blockIdx.x * blockDim.x + threadIdx.x;
    int stride = gridDim.x * blockDim.x;
    for (int i = tid; i < n0; i += stride) {
        float4 v = a0[i];
        v.x = (v.x < th) ? 0.0f : v.x;  v.y = (v.y < th) ? 0.0f : v.y;
        v.z = (v.z < th) ? 0.0f : v.z;  v.w = (v.w < th) ? 0.0f : v.w;
        out[i] = v;
    }
    float4* o1 = out + n0;
    for (int i = tid; i < n1; i += stride) {
        float4 v = a1[i];
        v.x = (v.x < th) ? 0.0f : v.x;  v.y = (v.y < th) ? 0.0f : v.y;
        v.z = (v.z < th) ? 0.0f : v.z;  v.w = (v.w < th) ? 0.0f : v.w;
        o1[i] = v;
    }
    float4* o2 = out + n0 + n1;
    for (int i = tid; i < n2; i += stride) {
        float4 v = a2[i];
        v.x = (v.x < th) ? 0.0f : v.x;  v.y = (v.y < th) ? 0.0f : v.y;
        v.z = (v.z < th) ? 0.0f : v.z;  v.w = (v.w < th) ? 0.0f : v.w;
        o2[i] = v;
    }
}

// ============================================================================
extern "C" void kernel_launch(void* const* d_in, const int* in_sizes, int n_in,
                              void* d_out, int out_size) {
    const float* e  = (const float*)d_in[0];
    const float* m  = (const float*)d_in[1];
    const float* dp = (const float*)d_in[2];
    const int* mf_ptr = (n_in >= 4) ? (const int*)d_in[3] : nullptr;
    int ne = in_sizes[0], nm = in_sizes[1], nd = in_sizes[2];
    long long ntot = (long long)ne + (long long)nm + (long long)nd;
    int ne4 = ne / 4, nm4 = nm / 4, nd4 = nd / 4;

    const uint4* u0 = (const uint4*)e;
    const uint4* u1 = (const uint4*)m;
    const uint4* u2 = (const uint4*)dp;

    k_init<<<1, 256>>>();
    k_spec_compact<<<NB, NT>>>(u0, ne4, u1, nm4, u2, nd4);
    k_select_spec<<<1, 256>>>(mf_ptr, 500000, ntot);

    // Fallback chain (device-gated; near-free when speculation holds)
    k_fb_hist256<<<NB, NT>>>(u0, ne4, u1, nm4, u2, nd4);
    k_fb_select<<<1, 256>>>(mf_ptr, 500000);
    k_fb_compact<<<NB, NT>>>(u0, ne4, u1, nm4, u2, nd4);

    // Radix passes over scratch
    k_hist_slices<<<NWARP / 8, NT>>>(24, 1);   // spec path only
    k_select8<<<1, 256>>>(0, 1);
    k_hist_slices<<<NWARP / 8, NT>>>(16, 0);
    k_select8<<<1, 256>>>(0, 0);
    k_hist_slices<<<NWARP / 8, NT>>>(8, 0);
    k_select8<<<1, 256>>>(0, 0);
    k_hist_slices<<<NWARP / 8, NT>>>(0, 0);
    k_select8<<<1, 256>>>(1, 0);

    k_threshold<<<2048, NT>>>((const float4*)e, ne4, (const float4*)m, nm4,
                              (const float4*)dp, nd4, (float4*)d_out);
}